// round 3
// baseline (speedup 1.0000x reference)
#include <cuda_runtime.h>
#include <math.h>

// Problem constants (fixed by the dataset)
#define Bsz 1024
#define Tn  200
#define LXn 190
#define LYn 50
#define Hd  256
#define XDd 64
#define YDd 64

#define GRID 128
#define NTHR 512
#define KC   16

typedef unsigned long long ull;

// ---------------- device scratch (module-static, allowed) -------------------
__device__ float g_h [Bsz*Hd];
__device__ float g_s [Bsz*Hd];
__device__ float g_tf[Bsz*Hd];
__device__ float g_hi[Bsz*Hd];
__device__ float g_tu[Bsz*Hd];
__device__ float g_tr[Bsz*Hd];
__device__ float g_u [Bsz*Hd];
__device__ float g_c1[Bsz*Hd];
__device__ float g_c2[Bsz*Hd];
__device__ float g_tn[Bsz*Hd];
__device__ float g_yb[(size_t)LYn*Bsz*Hd];   // saved new_y at the 50 query steps
__device__ float g_to[(size_t)LYn*Bsz*Hd];   // out-MLP hidden
__device__ float g_dt[Tn];
__device__ int   g_obs[Tn];
__device__ int   g_qm [Tn];
__device__ unsigned g_cnt;
__device__ unsigned g_gen;

// ---------------- packed f32x2 helpers --------------------------------------
__device__ __forceinline__ ull fma2(ull a, ull b, ull c) {
    ull d;
    asm("fma.rn.f32x2 %0, %1, %2, %3;" : "=l"(d) : "l"(a), "l"(b), "l"(c));
    return d;
}
__device__ __forceinline__ ull dup2(float x) {
    ull d;
    asm("mov.b64 %0, {%1, %1};" : "=l"(d) : "f"(x));
    return d;
}
__device__ __forceinline__ ull pk2(float lo, float hi) {
    ull d;
    asm("mov.b64 %0, {%1, %2};" : "=l"(d) : "f"(lo), "f"(hi));
    return d;
}

// ---------------- grid barrier (all 128 CTAs resident) ----------------------
__device__ __forceinline__ void gbar() {
    __syncthreads();
    if (threadIdx.x == 0) {
        __threadfence();
        volatile unsigned* vg = &g_gen;
        unsigned gen = *vg;
        if (atomicAdd(&g_cnt, 1u) == GRID - 1u) {
            atomicExch(&g_cnt, 0u);
            __threadfence();
            atomicExch((unsigned*)&g_gen, gen + 1u);
        } else {
            while (*vg == gen) { }
        }
        __threadfence();
    }
    __syncthreads();
}

// ---------------- A-operand sources ------------------------------------------
enum { SRC_H, SRC_TF, SRC_GI, SRC_TU, SRC_TR, SRC_CC, SRC_TN, SRC_YB, SRC_TO };
enum { EPI_TANH_TF, EPI_TANH_TU, EPI_TANH_TR, EPI_TANH_TN, EPI_TANH_TO,
       EPI_HI, EPI_U, EPI_R, EPI_NS, EPI_OUT };

__device__ __forceinline__ float loadA(int src, int m, int k, int obs,
                                       const float* __restrict__ xd,
                                       const float* __restrict__ xm) {
    switch (src) {
    case SRC_H:  return __ldcg(g_h  + m*Hd + k);
    case SRC_TF: return __ldcg(g_tf + m*Hd + k);
    case SRC_GI:
        if (k < Hd)   return __ldcg(g_hi + m*Hd + k);
        if (k < 2*Hd) return __ldcg(g_s  + m*Hd + (k - Hd));
        else {
            if (obs < 0) return 0.0f;
            int o = (m*LXn + obs)*XDd + (k - 2*Hd);
            return __ldg(xd + o) * __ldg(xm + o);
        }
    case SRC_TU: return __ldcg(g_tu + m*Hd + k);
    case SRC_TR: return __ldcg(g_tr + m*Hd + k);
    case SRC_CC:
        if (k < Hd)   return __ldcg(g_c1 + m*Hd + k);
        if (k < 2*Hd) return __ldcg(g_c2 + m*Hd + (k - Hd));
        else {
            if (obs < 0) return 0.0f;
            int o = (m*LXn + obs)*XDd + (k - 2*Hd);
            return __ldg(xd + o) * __ldg(xm + o);
        }
    case SRC_TN: return __ldcg(g_tn + m*Hd + k);
    case SRC_YB: return __ldcg(g_yb + (size_t)m*Hd + k);
    default:     return __ldcg(g_to + (size_t)m*Hd + k);
    }
}

// smem layout (union, 8192 floats = 32KB):
//   k-loop phase : group g in [0,4): As = sbuf + g*1664 (16 x stride36)
//                                    Bs = As + 576      (16 x stride68)
//   reduce phase : P[g] = sbuf + g*2048, layout [col][32 rows]
#define AS_STRIDE 36
#define BS_STRIDE 68
#define GRP_FLOATS 1664

// ---------------- one 32x64 output tile, 512 threads, split-K(4) -------------
__device__ __noinline__ void tile_gemm(float* sbuf,
                                       int src, int m0, int n0,
                                       const float* __restrict__ W, int ldw,
                                       const float* __restrict__ bias, int K,
                                       int epi, int obs, float dt, int q,
                                       const float* __restrict__ xd,
                                       const float* __restrict__ xm,
                                       float* __restrict__ dout)
{
    const int tid = threadIdx.x;
    const int kg  = tid >> 7;          // k-group 0..3
    const int gt  = tid & 127;
    const int ty  = gt >> 4;           // row-group 0..7  -> rows 4*ty..
    const int tx  = gt & 15;           // col-group 0..15 -> cols 4*tx..
    const int ml  = gt & 31;           // A-loader row
    const int kl0 = gt >> 5;           // A-loader k base (0..3)

    const int Kq = K >> 2;
    const int k0 = kg * Kq;
    float* As = sbuf + kg * GRP_FLOATS;
    float* Bs = As + 16 * AS_STRIDE;

    ull acc[2][4];
#pragma unroll
    for (int p = 0; p < 2; p++)
#pragma unroll
        for (int c = 0; c < 4; c++) acc[p][c] = 0ULL;

    float  aR[4];
    float4 bR[2];
    // prefetch chunk 0
#pragma unroll
    for (int p = 0; p < 4; p++)
        aR[p] = loadA(src, m0 + ml, k0 + kl0 + 4*p, obs, xd, xm);
#pragma unroll
    for (int p = 0; p < 2; p++) {
        int e = gt + p*128; int n4 = e & 15, kk = e >> 4;
        bR[p] = __ldg((const float4*)(W + (size_t)(k0 + kk)*ldw + n0 + n4*4));
    }

    for (int kb = k0; kb < k0 + Kq; kb += KC) {
        __syncthreads();
#pragma unroll
        for (int p = 0; p < 4; p++) As[(kl0 + 4*p)*AS_STRIDE + ml] = aR[p];
#pragma unroll
        for (int p = 0; p < 2; p++) {
            int e = gt + p*128; int n4 = e & 15, kk = e >> 4;
            *(float4*)&Bs[kk*BS_STRIDE + n4*4] = bR[p];
        }
        __syncthreads();
        int kn = kb + KC;
        if (kn < k0 + Kq) {
#pragma unroll
            for (int p = 0; p < 4; p++)
                aR[p] = loadA(src, m0 + ml, kn + kl0 + 4*p, obs, xd, xm);
#pragma unroll
            for (int p = 0; p < 2; p++) {
                int e = gt + p*128; int n4 = e & 15, kk = e >> 4;
                bR[p] = __ldg((const float4*)(W + (size_t)(kn + kk)*ldw + n0 + n4*4));
            }
        }
#pragma unroll
        for (int k = 0; k < KC; k++) {
            float4 av = *(const float4*)&As[k*AS_STRIDE + 4*ty];
            float4 bv = *(const float4*)&Bs[k*BS_STRIDE + 4*tx];
            ull a0 = pk2(av.x, av.y);
            ull a1 = pk2(av.z, av.w);
            acc[0][0] = fma2(a0, dup2(bv.x), acc[0][0]);
            acc[1][0] = fma2(a1, dup2(bv.x), acc[1][0]);
            acc[0][1] = fma2(a0, dup2(bv.y), acc[0][1]);
            acc[1][1] = fma2(a1, dup2(bv.y), acc[1][1]);
            acc[0][2] = fma2(a0, dup2(bv.z), acc[0][2]);
            acc[1][2] = fma2(a1, dup2(bv.z), acc[1][2]);
            acc[0][3] = fma2(a0, dup2(bv.w), acc[0][3]);
            acc[1][3] = fma2(a1, dup2(bv.w), acc[1][3]);
        }
    }

    // ---- cross-group reduction through smem ----
    __syncthreads();                   // all groups done with As/Bs
#pragma unroll
    for (int p = 0; p < 2; p++)
#pragma unroll
        for (int c = 0; c < 4; c++)
            *(ull*)&sbuf[kg*2048 + (4*tx + c)*32 + 4*ty + 2*p] = acc[p][c];
    __syncthreads();

    // ---- epilogue: 512 threads x 4 outputs ----
#pragma unroll
    for (int i = 0; i < 4; i++) {
        int idx = tid + i*512;
        int row = idx & 31, col = idx >> 5;
        int off = col*32 + row;
        float val = sbuf[off] + sbuf[2048 + off] + sbuf[4096 + off] + sbuf[6144 + off];
        int m = m0 + row, n = n0 + col;
        val += __ldg(bias + n);
        switch (epi) {
        case EPI_TANH_TF: __stcg(g_tf + m*Hd + n, tanhf(val)); break;
        case EPI_TANH_TU: __stcg(g_tu + m*Hd + n, tanhf(val)); break;
        case EPI_TANH_TR: __stcg(g_tr + m*Hd + n, tanhf(val)); break;
        case EPI_TANH_TN: __stcg(g_tn + m*Hd + n, tanhf(val)); break;
        case EPI_TANH_TO: __stcg(g_to + (size_t)m*Hd + n, tanhf(val)); break;
        case EPI_HI:
            __stcg(g_hi + m*Hd + n, __ldcg(g_h + m*Hd + n) + dt*val);
            break;
        case EPI_U:
            __stcg(g_u + m*Hd + n, 1.0f/(1.0f + expf(-val)));
            break;
        case EPI_R: {
            float rr = 1.0f/(1.0f + expf(-val));
            __stcg(g_c1 + m*Hd + n, __ldcg(g_hi + m*Hd + n) * rr);
            __stcg(g_c2 + m*Hd + n, __ldcg(g_s  + m*Hd + n) * rr);
        } break;
        case EPI_NS: {
            if (n < Hd) {
                float uu = __ldcg(g_u  + m*Hd + n);
                float hi = __ldcg(g_hi + m*Hd + n);
                float ny = (1.0f - uu)*val + uu*hi;
                __stcg(g_h + m*Hd + n, ny);
                if (q >= 0)
                    __stcg(g_yb + ((size_t)q*Bsz + m)*Hd + n, ny);
            } else {
                int nn = n - Hd;
                float uu = __ldcg(g_u + m*Hd + nn);
                float sv = __ldcg(g_s + m*Hd + nn);
                float nstd = fabsf((1.0f - uu)*fabsf(val) + uu*sv);
                __stcg(g_s + m*Hd + nn, nstd);
            }
        } break;
        case EPI_OUT: {
            int b = m & (Bsz - 1), qq = m >> 10;
            dout[((size_t)b*LYn + qq)*YDd + n] = val;
        } break;
        }
    }
    // no trailing sync needed: next tile's first __syncthreads orders reuse
}

// ---------------- init: dt / obs-slot / query maps ---------------------------
__global__ void init_kernel(const float* __restrict__ x_time,
                            const int* __restrict__ x_idx,
                            const int* __restrict__ y_idx) {
    int tid = threadIdx.x;
    for (int t = tid; t < Tn; t += blockDim.x) { g_obs[t] = -1; g_qm[t] = -1; }
    __syncthreads();
    for (int i = tid; i < LXn; i += blockDim.x) g_obs[x_idx[i]] = i;
    for (int j = tid; j < LYn; j += blockDim.x) g_qm[y_idx[j]] = j;
    __syncthreads();
    for (int t = tid; t < Tn; t += blockDim.x) {
        float d;
        float tlast = x_time[Tn - 1];
        if (t == 0)      d = tlast - (tlast + 0.01f);   // ti - prev_ti at step 0
        else if (t == 1) d = tlast - x_time[0];
        else             d = x_time[t - 2] - x_time[t - 1];
        g_dt[t] = d;
    }
}

// ---------------- persistent recurrence kernel -------------------------------
__global__ void __launch_bounds__(NTHR, 1)
recur_kernel(const float* __restrict__ xd, const float* __restrict__ xm,
             const float* ug_w1, const float* ug_b1, const float* ug_w2, const float* ug_b2,
             const float* rg_w1, const float* rg_b1, const float* rg_w2, const float* rg_b2,
             const float* ns_w1, const float* ns_b1, const float* ns_w2, const float* ns_b2,
             const float* out_w1, const float* out_b1, const float* out_w2, const float* out_b2,
             const float* f_w1, const float* f_b1, const float* f_w2, const float* f_b2,
             float* __restrict__ out)
{
    __shared__ float sbuf[8192];

    // zero initial state
    for (int i = blockIdx.x*NTHR + threadIdx.x; i < Bsz*Hd; i += GRID*NTHR) {
        __stcg(g_h + i, 0.0f);
        __stcg(g_s + i, 0.0f);
    }
    gbar();

    for (int t = 0; t < Tn; t++) {
        int obs = g_obs[t];
        int q   = g_qm[t];
        float dt = g_dt[t];

        // S1: t_f = tanh(h @ f_w1 + f_b1)                      [128 tiles]
        {
            int tl = blockIdx.x;
            tile_gemm(sbuf, SRC_H, (tl >> 2)*32, (tl & 3)*64,
                      f_w1, Hd, f_b1, Hd, EPI_TANH_TF, obs, dt, q, xd, xm, g_tf);
        }
        gbar();

        // S2: hi = h + dt*(t_f @ f_w2 + f_b2)                  [128 tiles]
        {
            int tl = blockIdx.x;
            tile_gemm(sbuf, SRC_TF, (tl >> 2)*32, (tl & 3)*64,
                      f_w2, Hd, f_b2, Hd, EPI_HI, obs, dt, q, xd, xm, g_hi);
        }
        gbar();

        // S3: t_u / t_r = tanh([hi,s,x] @ {ug,rg}_w1 + b)      [256 tiles]
        for (int tl = blockIdx.x; tl < 256; tl += GRID) {
            int hh = tl >> 7, t2 = tl & 127;
            tile_gemm(sbuf, SRC_GI, (t2 >> 2)*32, (t2 & 3)*64,
                      hh ? rg_w1 : ug_w1, Hd, hh ? rg_b1 : ug_b1, 2*Hd + XDd,
                      hh ? EPI_TANH_TR : EPI_TANH_TU, obs, dt, q, xd, xm, g_tu);
        }
        gbar();

        // S4: u = sig(t_u@ug_w2+b) ; r-side: c1=hi*r, c2=s*r   [256 tiles]
        for (int tl = blockIdx.x; tl < 256; tl += GRID) {
            int hh = tl >> 7, t2 = tl & 127;
            tile_gemm(sbuf, hh ? SRC_TR : SRC_TU, (t2 >> 2)*32, (t2 & 3)*64,
                      hh ? rg_w2 : ug_w2, Hd, hh ? rg_b2 : ug_b2, Hd,
                      hh ? EPI_R : EPI_U, obs, dt, q, xd, xm, g_u);
        }
        gbar();

        // S5: t_n = tanh([c1,c2,x] @ ns_w1 + b)                [128 tiles]
        {
            int tl = blockIdx.x;
            tile_gemm(sbuf, SRC_CC, (tl >> 2)*32, (tl & 3)*64,
                      ns_w1, Hd, ns_b1, 2*Hd + XDd, EPI_TANH_TN, obs, dt, q, xd, xm, g_tn);
        }
        gbar();

        // S6: ns = t_n @ ns_w2 + b (N=512), gated state update [256 tiles]
        for (int tl = blockIdx.x; tl < 256; tl += GRID)
            tile_gemm(sbuf, SRC_TN, (tl >> 3)*32, (tl & 7)*64,
                      ns_w2, 2*Hd, ns_b2, Hd, EPI_NS, obs, dt, q, xd, xm, g_h);
        gbar();
    }

    // O1: t_o = tanh(yb @ out_w1 + b1), M = 50*1024            [6400 tiles]
    for (int tl = blockIdx.x; tl < (LYn*Bsz/32)*4; tl += GRID)
        tile_gemm(sbuf, SRC_YB, (tl >> 2)*32, (tl & 3)*64,
                  out_w1, Hd, out_b1, Hd, EPI_TANH_TO, -1, 0.0f, -1, xd, xm, g_to);
    gbar();

    // O2: out = t_o @ out_w2 + b2  (N=64)                      [1600 tiles]
    for (int tl = blockIdx.x; tl < LYn*Bsz/32; tl += GRID)
        tile_gemm(sbuf, SRC_TO, tl*32, 0,
                  out_w2, YDd, out_b2, Hd, EPI_OUT, -1, 0.0f, -1, xd, xm, out);
}

// ---------------- launch ------------------------------------------------------
extern "C" void kernel_launch(void* const* d_in, const int* in_sizes, int n_in,
                              void* d_out, int out_size) {
    (void)in_sizes; (void)n_in; (void)out_size;
    const float* xd  = (const float*)d_in[0];
    const float* xm  = (const float*)d_in[1];
    const float* xt  = (const float*)d_in[2];
    const int*   xti = (const int*)d_in[3];
    const int*   yti = (const int*)d_in[4];

    init_kernel<<<1, 256>>>(xt, xti, yti);

    recur_kernel<<<GRID, NTHR>>>(
        xd, xm,
        (const float*)d_in[5],  (const float*)d_in[6],  (const float*)d_in[7],  (const float*)d_in[8],
        (const float*)d_in[9],  (const float*)d_in[10], (const float*)d_in[11], (const float*)d_in[12],
        (const float*)d_in[13], (const float*)d_in[14], (const float*)d_in[15], (const float*)d_in[16],
        (const float*)d_in[17], (const float*)d_in[18], (const float*)d_in[19], (const float*)d_in[20],
        (const float*)d_in[21], (const float*)d_in[22], (const float*)d_in[23], (const float*)d_in[24],
        (float*)d_out);
}

// round 6
// speedup vs baseline: 3.2586x; 3.2586x over previous
#include <cuda_runtime.h>
#include <math.h>

// Problem constants (fixed by the dataset)
#define Bsz 1024
#define Tn  200
#define LXn 190
#define LYn 50
#define Hd  256
#define XDd 64
#define YDd 64

#define GRID 128
#define NTHR 256
#define ROWS 8

typedef unsigned long long ull;

// ---------------- device scratch ---------------------------------------------
// saved new_y at query steps, per-CTA transposed: [q][cta][col][8rows]
__device__ float g_ybT[(size_t)LYn*GRID*Hd*ROWS];
__device__ float g_dt[Tn];
__device__ int   g_obs[Tn];
__device__ int   g_qm [Tn];

// ---------------- packed f32x2 helpers ---------------------------------------
__device__ __forceinline__ ull fma2(ull a, ull b, ull c) {
    ull d;
    asm("fma.rn.f32x2 %0, %1, %2, %3;" : "=l"(d) : "l"(a), "l"(b), "l"(c));
    return d;
}
__device__ __forceinline__ ull dup2(float x) {
    ull d;
    asm("mov.b64 %0, {%1, %1};" : "=l"(d) : "f"(x));
    return d;
}
__device__ __forceinline__ void unpk(ull u, float& lo, float& hi) {
    asm("mov.b64 {%0, %1}, %2;" : "=f"(lo), "=f"(hi) : "l"(u));
}

__device__ __forceinline__ float sigm(float x) {
    return __fdividef(1.0f, 1.0f + __expf(-x));
}
__device__ __forceinline__ float tanh_f(float x) {
    // tanh(x) = 2*sigmoid(2x) - 1 ; |err| ~1e-6, far within 1e-3 budget
    return fmaf(2.0f, sigm(2.0f*x), -1.0f);
}

__device__ __forceinline__ void store8(float* p, const float v[8]) {
    *(float4*)p       = make_float4(v[0], v[1], v[2], v[3]);
    *(float4*)(p + 4) = make_float4(v[4], v[5], v[6], v[7]);
}

// ---------------- GEMM cores --------------------------------------------------
// As: transposed activations [k][8 rows], stride 8 floats, smem.
// Computes v[r] = sum_k As[k][r] * Wc[k*ldw]   (Wc already offset to this col)
// K must be a multiple of 16.
__device__ __forceinline__ void gemm1(const float* __restrict__ As, int K,
                                      const float* __restrict__ Wc, int ldw,
                                      float v[8])
{
    ull a0 = 0, a1 = 0, a2 = 0, a3 = 0;
    float w0[8], w1[8];
#pragma unroll
    for (int p = 0; p < 8; p++) w0[p] = __ldg(Wc + p*ldw);

    for (int kb = 0; kb < K; kb += 16) {
#pragma unroll
        for (int p = 0; p < 8; p++) w1[p] = __ldg(Wc + (size_t)(kb + 8 + p)*ldw);
#pragma unroll
        for (int kk = 0; kk < 8; kk++) {
            const float* ap = As + (kb + kk)*8;
            ulonglong2 A0 = *(const ulonglong2*)ap;
            ulonglong2 A1 = *(const ulonglong2*)(ap + 4);
            ull wb = dup2(w0[kk]);
            a0 = fma2(A0.x, wb, a0);
            a1 = fma2(A0.y, wb, a1);
            a2 = fma2(A1.x, wb, a2);
            a3 = fma2(A1.y, wb, a3);
        }
        if (kb + 16 < K) {
#pragma unroll
            for (int p = 0; p < 8; p++) w0[p] = __ldg(Wc + (size_t)(kb + 16 + p)*ldw);
        }
#pragma unroll
        for (int kk = 0; kk < 8; kk++) {
            const float* ap = As + (kb + 8 + kk)*8;
            ulonglong2 A0 = *(const ulonglong2*)ap;
            ulonglong2 A1 = *(const ulonglong2*)(ap + 4);
            ull wb = dup2(w1[kk]);
            a0 = fma2(A0.x, wb, a0);
            a1 = fma2(A0.y, wb, a1);
            a2 = fma2(A1.x, wb, a2);
            a3 = fma2(A1.y, wb, a3);
        }
    }
    unpk(a0, v[0], v[1]);
    unpk(a1, v[2], v[3]);
    unpk(a2, v[4], v[5]);
    unpk(a3, v[6], v[7]);
}

// Two output columns sharing the same A stream (FMA/LSU balanced).
__device__ __forceinline__ void gemm2(const float* __restrict__ As, int K,
                                      const float* __restrict__ Wa,
                                      const float* __restrict__ Wb, int ldw,
                                      float va[8], float vb[8])
{
    ull a0 = 0, a1 = 0, a2 = 0, a3 = 0;
    ull b0 = 0, b1 = 0, b2 = 0, b3 = 0;
    float wa0[8], wa1[8], wb0[8], wb1[8];
#pragma unroll
    for (int p = 0; p < 8; p++) {
        wa0[p] = __ldg(Wa + p*ldw);
        wb0[p] = __ldg(Wb + p*ldw);
    }
    for (int kb = 0; kb < K; kb += 16) {
#pragma unroll
        for (int p = 0; p < 8; p++) {
            wa1[p] = __ldg(Wa + (size_t)(kb + 8 + p)*ldw);
            wb1[p] = __ldg(Wb + (size_t)(kb + 8 + p)*ldw);
        }
#pragma unroll
        for (int kk = 0; kk < 8; kk++) {
            const float* ap = As + (kb + kk)*8;
            ulonglong2 A0 = *(const ulonglong2*)ap;
            ulonglong2 A1 = *(const ulonglong2*)(ap + 4);
            ull wA = dup2(wa0[kk]);
            ull wB = dup2(wb0[kk]);
            a0 = fma2(A0.x, wA, a0); b0 = fma2(A0.x, wB, b0);
            a1 = fma2(A0.y, wA, a1); b1 = fma2(A0.y, wB, b1);
            a2 = fma2(A1.x, wA, a2); b2 = fma2(A1.x, wB, b2);
            a3 = fma2(A1.y, wA, a3); b3 = fma2(A1.y, wB, b3);
        }
        if (kb + 16 < K) {
#pragma unroll
            for (int p = 0; p < 8; p++) {
                wa0[p] = __ldg(Wa + (size_t)(kb + 16 + p)*ldw);
                wb0[p] = __ldg(Wb + (size_t)(kb + 16 + p)*ldw);
            }
        }
#pragma unroll
        for (int kk = 0; kk < 8; kk++) {
            const float* ap = As + (kb + 8 + kk)*8;
            ulonglong2 A0 = *(const ulonglong2*)ap;
            ulonglong2 A1 = *(const ulonglong2*)(ap + 4);
            ull wA = dup2(wa1[kk]);
            ull wB = dup2(wb1[kk]);
            a0 = fma2(A0.x, wA, a0); b0 = fma2(A0.x, wB, b0);
            a1 = fma2(A0.y, wA, a1); b1 = fma2(A0.y, wB, b1);
            a2 = fma2(A1.x, wA, a2); b2 = fma2(A1.x, wB, b2);
            a3 = fma2(A1.y, wA, a3); b3 = fma2(A1.y, wB, b3);
        }
    }
    unpk(a0, va[0], va[1]); unpk(b0, vb[0], vb[1]);
    unpk(a1, va[2], va[3]); unpk(b1, vb[2], vb[3]);
    unpk(a2, va[4], va[5]); unpk(b2, vb[4], vb[5]);
    unpk(a3, va[6], va[7]); unpk(b3, vb[6], vb[7]);
}

// ---------------- init: dt / obs-slot / query maps ---------------------------
__global__ void init_kernel(const float* __restrict__ x_time,
                            const int* __restrict__ x_idx,
                            const int* __restrict__ y_idx) {
    int tid = threadIdx.x;
    for (int t = tid; t < Tn; t += blockDim.x) { g_obs[t] = -1; g_qm[t] = -1; }
    __syncthreads();
    for (int i = tid; i < LXn; i += blockDim.x) g_obs[x_idx[i]] = i;
    for (int j = tid; j < LYn; j += blockDim.x) g_qm[y_idx[j]] = j;
    __syncthreads();
    for (int t = tid; t < Tn; t += blockDim.x) {
        float d;
        float tlast = x_time[Tn - 1];
        if (t == 0)      d = tlast - (tlast + 0.01f);   // ti - prev_ti at step 0
        else if (t == 1) d = tlast - x_time[0];
        else             d = x_time[t - 2] - x_time[t - 1];
        g_dt[t] = d;
    }
}

// ---------------- smem layout (floats) ----------------------------------------
// sA   [576][8]  cat(hi, s, x)        0     .. 4608
// sC   [576][8]  cat(c1, c2, x)       4608  .. 9216
// sH   [256][8]  h                    9216  .. 11264
// sS   [256][8]  s                    11264 .. 13312
// sTF  [256][8]  tanh buf / f-hidden  13312 .. 15360
// sTU  [256][8]                       15360 .. 17408
// sTR  [256][8]                       17408 .. 19456
// sTN  [256][8]                       19456 .. 21504
// sU   [256][8]                       21504 .. 23552
#define SMEM_FLOATS 23552

// ---------------- persistent per-CTA recurrence -------------------------------
__global__ void __launch_bounds__(NTHR, 1)
recur_kernel(const float* __restrict__ xd, const float* __restrict__ xm,
             const float* __restrict__ ug_w1, const float* __restrict__ ug_b1,
             const float* __restrict__ ug_w2, const float* __restrict__ ug_b2,
             const float* __restrict__ rg_w1, const float* __restrict__ rg_b1,
             const float* __restrict__ rg_w2, const float* __restrict__ rg_b2,
             const float* __restrict__ ns_w1, const float* __restrict__ ns_b1,
             const float* __restrict__ ns_w2, const float* __restrict__ ns_b2,
             const float* __restrict__ out_w1, const float* __restrict__ out_b1,
             const float* __restrict__ out_w2, const float* __restrict__ out_b2,
             const float* __restrict__ f_w1, const float* __restrict__ f_b1,
             const float* __restrict__ f_w2, const float* __restrict__ f_b2,
             float* __restrict__ out)
{
    extern __shared__ float sm[];
    float* sA  = sm;
    float* sC  = sm + 4608;
    float* sH  = sm + 9216;
    float* sS  = sm + 11264;
    float* sTF = sm + 13312;
    float* sTU = sm + 15360;
    float* sTR = sm + 17408;
    float* sTN = sm + 19456;
    float* sU  = sm + 21504;

    const int tid = threadIdx.x;
    const int cta = blockIdx.x;
    const int m0  = cta * ROWS;

    // zero h, s
    for (int i = tid; i < 2048; i += NTHR) { sH[i] = 0.0f; sS[i] = 0.0f; }
    __syncthreads();

    float v[8];

    for (int t = 0; t < Tn; t++) {
        const int   obs = g_obs[t];
        const int   q   = g_qm[t];
        const float dt  = g_dt[t];

        // ---- step prologue: s -> sA[256:512]; x -> sA/sC[512:576] ----
        {
            float4 s0 = *(float4*)&sS[tid*8];
            float4 s1 = *(float4*)&sS[tid*8 + 4];
            *(float4*)&sA[(256 + tid)*8]     = s0;
            *(float4*)&sA[(256 + tid)*8 + 4] = s1;
        }
        if (tid < XDd) {
            float xv[8];
            if (obs >= 0) {
#pragma unroll
                for (int r = 0; r < 8; r++) {
                    int off = ((m0 + r)*LXn + obs)*XDd + tid;
                    xv[r] = __ldg(xd + off) * __ldg(xm + off);
                }
            } else {
#pragma unroll
                for (int r = 0; r < 8; r++) xv[r] = 0.0f;
            }
            store8(&sA[(512 + tid)*8], xv);
            store8(&sC[(512 + tid)*8], xv);
        }
        __syncthreads();

        // ---- S1: tf = tanh(h @ f_w1 + b1) ----
        gemm1(sH, 256, f_w1 + tid, Hd, v);
        {
            float b = __ldg(f_b1 + tid);
#pragma unroll
            for (int r = 0; r < 8; r++) v[r] = tanh_f(v[r] + b);
            store8(&sTF[tid*8], v);
        }
        __syncthreads();

        // ---- S2: hi = h + dt*(tf @ f_w2 + b2) -> sA[0:256] ----
        gemm1(sTF, 256, f_w2 + tid, Hd, v);
        {
            float b = __ldg(f_b2 + tid);
#pragma unroll
            for (int r = 0; r < 8; r++) v[r] = sH[tid*8 + r] + dt*(v[r] + b);
            store8(&sA[tid*8], v);
        }
        __syncthreads();

        // ---- S3 (fused): tu = tanh(cat@ug_w1+b), tr = tanh(cat@rg_w1+b) ----
        {
            float vb_[8];
            gemm2(sA, 576, ug_w1 + tid, rg_w1 + tid, Hd, v, vb_);
            float bu = __ldg(ug_b1 + tid), br = __ldg(rg_b1 + tid);
#pragma unroll
            for (int r = 0; r < 8; r++) {
                v[r]   = tanh_f(v[r] + bu);
                vb_[r] = tanh_f(vb_[r] + br);
            }
            store8(&sTU[tid*8], v);
            store8(&sTR[tid*8], vb_);
        }
        __syncthreads();

        // ---- S4a: u = sigmoid(tu @ ug_w2 + b) ----
        gemm1(sTU, 256, ug_w2 + tid, Hd, v);
        {
            float b = __ldg(ug_b2 + tid);
#pragma unroll
            for (int r = 0; r < 8; r++) v[r] = sigm(v[r] + b);
            store8(&sU[tid*8], v);
        }
        // (no sync needed: S4b reads sTR / writes sC — disjoint from S4a)

        // ---- S4b: r = sigmoid(tr @ rg_w2 + b); c1 = hi*r, c2 = s*r ----
        gemm1(sTR, 256, rg_w2 + tid, Hd, v);
        {
            float b = __ldg(rg_b2 + tid);
            float c1[8], c2[8];
#pragma unroll
            for (int r = 0; r < 8; r++) {
                float rr = sigm(v[r] + b);
                c1[r] = sA[tid*8 + r] * rr;
                c2[r] = sA[(256 + tid)*8 + r] * rr;
            }
            store8(&sC[tid*8], c1);
            store8(&sC[(256 + tid)*8], c2);
        }
        __syncthreads();

        // ---- S5: tn = tanh(cc @ ns_w1 + b) ----
        gemm1(sC, 576, ns_w1 + tid, Hd, v);
        {
            float b = __ldg(ns_b1 + tid);
#pragma unroll
            for (int r = 0; r < 8; r++) v[r] = tanh_f(v[r] + b);
            store8(&sTN[tid*8], v);
        }
        __syncthreads();

        // ---- S6 (fused N=512): ns | ns_std, gated state update ----
        {
            float vs[8];
            gemm2(sTN, 256, ns_w2 + tid, ns_w2 + tid + Hd, 2*Hd, v, vs);
            float b1_ = __ldg(ns_b2 + tid), b2_ = __ldg(ns_b2 + tid + Hd);
            float hy[8], sy[8];
#pragma unroll
            for (int r = 0; r < 8; r++) {
                float u_  = sU[tid*8 + r];
                float hi_ = sA[tid*8 + r];
                float so_ = sA[(256 + tid)*8 + r];
                float ns_ = v[r] + b1_;
                float sd_ = fabsf(vs[r] + b2_);
                hy[r] = (1.0f - u_)*ns_ + u_*hi_;
                sy[r] = fabsf((1.0f - u_)*sd_ + u_*so_);
            }
            store8(&sH[tid*8], hy);
            store8(&sS[tid*8], sy);
            if (q >= 0) {
                float* d = g_ybT + (((size_t)q*GRID + cta)*Hd + tid)*8;
                *(float4*)d       = make_float4(hy[0], hy[1], hy[2], hy[3]);
                *(float4*)(d + 4) = make_float4(hy[4], hy[5], hy[6], hy[7]);
            }
        }
        __syncthreads();
    }

    // ---- deferred out-MLP: per-CTA, 50 query states ----
    for (int q = 0; q < LYn; q++) {
        const float4* src = (const float4*)(g_ybT + ((size_t)q*GRID + cta)*Hd*8);
        float4* dstA = (float4*)sA;
        for (int i = tid; i < 512; i += NTHR) dstA[i] = src[i];
        __syncthreads();

        gemm1(sA, 256, out_w1 + tid, Hd, v);
        {
            float b = __ldg(out_b1 + tid);
#pragma unroll
            for (int r = 0; r < 8; r++) v[r] = tanh_f(v[r] + b);
            store8(&sTF[tid*8], v);
        }
        __syncthreads();

        if (tid < YDd) {
            gemm1(sTF, 256, out_w2 + tid, YDd, v);
            float b = __ldg(out_b2 + tid);
#pragma unroll
            for (int r = 0; r < 8; r++)
                out[((size_t)(m0 + r)*LYn + q)*YDd + tid] = v[r] + b;
        }
        __syncthreads();
    }
}

// ---------------- launch ------------------------------------------------------
extern "C" void kernel_launch(void* const* d_in, const int* in_sizes, int n_in,
                              void* d_out, int out_size) {
    (void)in_sizes; (void)n_in; (void)out_size;
    const float* xd  = (const float*)d_in[0];
    const float* xm  = (const float*)d_in[1];
    const float* xt  = (const float*)d_in[2];
    const int*   xti = (const int*)d_in[3];
    const int*   yti = (const int*)d_in[4];

    // Unconditional (idempotent, non-stream API; no static guards allowed)
    cudaFuncSetAttribute(recur_kernel,
                         cudaFuncAttributeMaxDynamicSharedMemorySize,
                         SMEM_FLOATS * (int)sizeof(float));

    init_kernel<<<1, 256>>>(xt, xti, yti);

    recur_kernel<<<GRID, NTHR, SMEM_FLOATS * sizeof(float)>>>(
        xd, xm,
        (const float*)d_in[5],  (const float*)d_in[6],  (const float*)d_in[7],  (const float*)d_in[8],
        (const float*)d_in[9],  (const float*)d_in[10], (const float*)d_in[11], (const float*)d_in[12],
        (const float*)d_in[13], (const float*)d_in[14], (const float*)d_in[15], (const float*)d_in[16],
        (const float*)d_in[17], (const float*)d_in[18], (const float*)d_in[19], (const float*)d_in[20],
        (const float*)d_in[21], (const float*)d_in[22], (const float*)d_in[23], (const float*)d_in[24],
        (float*)d_out);
}